// round 2
// baseline (speedup 1.0000x reference)
#include <cuda_runtime.h>

#define TPB  256
#define ROWS 16

__device__ __forceinline__ float tanha(float x) {
    float y;
    asm("tanh.approx.f32 %0, %1;" : "=f"(y) : "f"(x));
    return y;
}

__global__ void __launch_bounds__(TPB, 2) qnn_kernel(
    const float2* __restrict__ in,
    const float*  __restrict__ gW1, const float* __restrict__ gb1,
    const float*  __restrict__ gW2, const float* __restrict__ gb2,
    const float*  __restrict__ gW3, const float* __restrict__ gb3,
    const float*  __restrict__ gw,
    float* __restrict__ out, int nrows, int tstride)
{
    // Load the tiny model into registers once per thread (broadcast loads,
    // amortized over ROWS rows).
    float W1[3][8], B1[8], W2[8][4], B2[4], W3[4];
#pragma unroll
    for (int i = 0; i < 3; ++i)
#pragma unroll
        for (int j = 0; j < 8; ++j) W1[i][j] = __ldg(gW1 + i * 8 + j);
#pragma unroll
    for (int j = 0; j < 8; ++j) B1[j] = __ldg(gb1 + j);
#pragma unroll
    for (int i = 0; i < 8; ++i)
#pragma unroll
        for (int j = 0; j < 4; ++j) W2[i][j] = __ldg(gW2 + i * 4 + j);
#pragma unroll
    for (int j = 0; j < 4; ++j) B2[j] = __ldg(gb2 + j);
#pragma unroll
    for (int j = 0; j < 4; ++j) W3[j] = __ldg(gW3 + j);
    const float B3 = __ldg(gb3);
    const float wq = __ldg(gw);

    const int t = blockIdx.x * TPB + threadIdx.x;
    if (t >= tstride) return;

    // Fast path: all ROWS iterations in-bounds (true for every thread when
    // nrows % ROWS == 0, which holds for the production shape). Tail threads
    // fall back to the guarded loop.
    const bool full = (t + (ROWS - 1) * tstride) < nrows;

    if (full) {
#pragma unroll 4
        for (int k = 0; k < ROWS; ++k) {
            const int r = t + k * tstride;       // coalesced: lanes adjacent
            const float2 p = __ldg(in + r);

            // quantum feature: sin(x0) * sin(x1 + w)
            const float q = __sinf(p.x) * __sinf(p.y + wq);

            // layer 1: [x0, x1, q] @ W1 + b1 -> tanh
            float h1[8];
#pragma unroll
            for (int j = 0; j < 8; ++j) {
                float a = fmaf(W1[0][j], p.x, B1[j]);
                a = fmaf(W1[1][j], p.y, a);
                a = fmaf(W1[2][j], q, a);
                h1[j] = tanha(a);
            }

            // layer 2: h1 @ W2 + b2 -> tanh
            float h2[4];
#pragma unroll
            for (int j = 0; j < 4; ++j) {
                float a = B2[j];
#pragma unroll
                for (int i = 0; i < 8; ++i) a = fmaf(h1[i], W2[i][j], a);
                h2[j] = tanha(a);
            }

            // layer 3: h2 @ W3 + b3
            float o = B3;
#pragma unroll
            for (int j = 0; j < 4; ++j) o = fmaf(h2[j], W3[j], o);

            out[r] = o;
        }
    } else {
        for (int k = 0; k < ROWS; ++k) {
            const int r = t + k * tstride;
            if (r >= nrows) break;
            const float2 p = __ldg(in + r);
            const float q = __sinf(p.x) * __sinf(p.y + wq);
            float h1[8];
#pragma unroll
            for (int j = 0; j < 8; ++j) {
                float a = fmaf(W1[0][j], p.x, B1[j]);
                a = fmaf(W1[1][j], p.y, a);
                a = fmaf(W1[2][j], q, a);
                h1[j] = tanha(a);
            }
            float h2[4];
#pragma unroll
            for (int j = 0; j < 4; ++j) {
                float a = B2[j];
#pragma unroll
                for (int i = 0; i < 8; ++i) a = fmaf(h1[i], W2[i][j], a);
                h2[j] = tanha(a);
            }
            float o = B3;
#pragma unroll
            for (int j = 0; j < 4; ++j) o = fmaf(h2[j], W3[j], o);
            out[r] = o;
        }
    }
}

extern "C" void kernel_launch(void* const* d_in, const int* in_sizes, int n_in,
                              void* d_out, int out_size)
{
    const float* in = (const float*)d_in[0];
    const int B = in_sizes[0] / 2;                     // rows
    const int tstride = (B + ROWS - 1) / ROWS;         // threads needed
    const int blocks = (tstride + TPB - 1) / TPB;

    qnn_kernel<<<blocks, TPB>>>(
        (const float2*)in,
        (const float*)d_in[1], (const float*)d_in[2],
        (const float*)d_in[3], (const float*)d_in[4],
        (const float*)d_in[5], (const float*)d_in[6],
        (const float*)d_in[7],
        (float*)d_out, B, tstride);
}